// round 1
// baseline (speedup 1.0000x reference)
#include <cuda_runtime.h>

#define NN 50000
#define NE 1600000
#define IND 128
#define HD 64
#define NR 5
#define SA_STRIDE 68
#define NEG_SLOPE 0.01f

// ---- scratch (device globals; no allocation allowed) ----
__device__ float g_w[NE];                       // per-edge weight w_e (layer-independent)
__device__ float g_S[NN * NR];                  // S[n][r] = sum of w_e over edges into n with type r
__device__ float g_emb0[NN * HD];
__device__ float g_emb1[NN * HD];
__device__ float g_emb2[NN * HD];
__device__ float g_T[(size_t)10 * NN * HD];     // TA_r at idx r (0..4), TB_r at idx 5+r  (128 MB)
__device__ float g_acc[NN * HD];                // scatter accumulator

// ---------------------------------------------------------------------------
__global__ void k_init() {
  int stride = gridDim.x * blockDim.x;
  int t = blockIdx.x * blockDim.x + threadIdx.x;
  for (int i = t; i < NN * NR; i += stride) g_S[i] = 0.f;
  for (int i = t; i < NN * HD; i += stride) g_acc[i] = 0.f;
}

// w_e = lam * exp(-beta*|t_e|);  S[dst][r] += w_e   (both layer-independent)
__global__ void k_wS(const float* __restrict__ etime, const int* __restrict__ eidx,
                     const int* __restrict__ etype, const float* __restrict__ plam,
                     const float* __restrict__ pbeta) {
  int e = blockIdx.x * blockDim.x + threadIdx.x;
  if (e >= NE) return;
  float w = plam[0] * expf(-pbeta[0] * fabsf(etime[e]));
  g_w[e] = w;
  int d = eidx[NE + e];
  int r = etype[e];
  atomicAdd(&g_S[d * NR + r], w);
}

// ---------------------------------------------------------------------------
// Tiled fp32 GEMM helper: 64-row tile x 64 cols, 256 threads, 4x4 register tile.
// A: [NN, K] row-major. W: [K, 64] row-major. Accumulates into acc[4][4].
__device__ __forceinline__ void gemm_accum(
    const float* __restrict__ A, int K, const float* __restrict__ W,
    int row0, float* sA, float* sW, float acc[4][4], int tx, int ty) {
  for (int k0 = 0; k0 < K; k0 += 64) {
    __syncthreads();
    #pragma unroll 1
    for (int i = threadIdx.x; i < 1024; i += 256)
      ((float4*)sW)[i] = *((const float4*)(W + (size_t)k0 * HD) + i);
    #pragma unroll 1
    for (int i = threadIdx.x; i < 1024; i += 256) {
      int r = i >> 4, c = i & 15;
      int row = row0 + r;
      float4 v = make_float4(0.f, 0.f, 0.f, 0.f);
      if (row < NN) v = *(const float4*)(A + (size_t)row * K + k0 + c * 4);
      *(float4*)(sA + r * SA_STRIDE + c * 4) = v;
    }
    __syncthreads();
    #pragma unroll 16
    for (int k = 0; k < 64; k++) {
      float4 wv = ((const float4*)sW)[k * 16 + tx];
      float a0 = sA[(ty * 4 + 0) * SA_STRIDE + k];
      float a1 = sA[(ty * 4 + 1) * SA_STRIDE + k];
      float a2 = sA[(ty * 4 + 2) * SA_STRIDE + k];
      float a3 = sA[(ty * 4 + 3) * SA_STRIDE + k];
      acc[0][0] += a0 * wv.x; acc[0][1] += a0 * wv.y; acc[0][2] += a0 * wv.z; acc[0][3] += a0 * wv.w;
      acc[1][0] += a1 * wv.x; acc[1][1] += a1 * wv.y; acc[1][2] += a1 * wv.z; acc[1][3] += a1 * wv.w;
      acc[2][0] += a2 * wv.x; acc[2][1] += a2 * wv.y; acc[2][2] += a2 * wv.z; acc[2][3] += a2 * wv.w;
      acc[3][0] += a3 * wv.x; acc[3][1] += a3 * wv.y; acc[3][2] += a3 * wv.z; acc[3][3] += a3 * wv.w;
    }
  }
}

// emb0 = x @ field_W + field_b
__global__ void k_emb0(const float* __restrict__ x, const float* __restrict__ fW,
                       const float* __restrict__ fb) {
  __shared__ __align__(16) float sA[64 * SA_STRIDE];
  __shared__ __align__(16) float sW[64 * 64];
  __shared__ float sb[64];
  if (threadIdx.x < 64) sb[threadIdx.x] = fb[threadIdx.x];
  int tx = threadIdx.x & 15, ty = threadIdx.x >> 4;
  int row0 = blockIdx.x * 64;
  float acc[4][4] = {};
  gemm_accum(x, IND, fW, row0, sA, sW, acc, tx, ty);
  #pragma unroll
  for (int i = 0; i < 4; i++) {
    int row = row0 + ty * 4 + i;
    if (row < NN) {
      float4 o = make_float4(acc[i][0] + sb[tx * 4 + 0], acc[i][1] + sb[tx * 4 + 1],
                             acc[i][2] + sb[tx * 4 + 2], acc[i][3] + sb[tx * 4 + 3]);
      *(float4*)(g_emb0 + (size_t)row * HD + tx * 4) = o;
    }
  }
}

// T[idx] = emb @ W_slice   for idx = half*5 + r  (half 0 -> A_r, half 1 -> B_r)
__global__ void k_trans(const float* __restrict__ relW, int layer) {
  __shared__ __align__(16) float sA[64 * SA_STRIDE];
  __shared__ __align__(16) float sW[64 * 64];
  const float* emb = (layer == 0) ? g_emb0 : g_emb1;
  int idx = blockIdx.y;
  int r = idx % 5, half = idx / 5;
  const float* W = relW + ((size_t)r * (2 * HD) + half * HD) * HD;
  int tx = threadIdx.x & 15, ty = threadIdx.x >> 4;
  int row0 = blockIdx.x * 64;
  float acc[4][4] = {};
  gemm_accum(emb, HD, W, row0, sA, sW, acc, tx, ty);
  float* out = g_T + (size_t)idx * NN * HD;
  #pragma unroll
  for (int i = 0; i < 4; i++) {
    int row = row0 + ty * 4 + i;
    if (row < NN) {
      float4 o = make_float4(acc[i][0], acc[i][1], acc[i][2], acc[i][3]);
      *(float4*)(out + (size_t)row * HD + tx * 4) = o;
    }
  }
}

// Per-edge scatter: acc[dst] += w_e * TA[r][src]. 16 lanes per edge, red.v4 atomics.
__global__ void k_edge(const int* __restrict__ eidx, const int* __restrict__ etype) {
  int gid = blockIdx.x * 256 + threadIdx.x;
  int e = gid >> 4;
  int lane = gid & 15;
  int s = __ldg(&eidx[e]);
  int d = __ldg(&eidx[NE + e]);
  int r = __ldg(&etype[e]);
  float w = __ldg(&g_w[e]);
  const float4* rowp = (const float4*)(g_T + ((size_t)r * NN + s) * HD);
  float4 v = __ldg(rowp + lane);
  float* dp = g_acc + (size_t)d * HD + lane * 4;
  asm volatile("red.global.add.v4.f32 [%0], {%1,%2,%3,%4};"
               :: "l"(dp), "f"(v.x * w), "f"(v.y * w), "f"(v.z * w), "f"(v.w * w)
               : "memory");
}

// emb_out[n] = acc[n] + sum_r S[n][r]*(TB_r[n] + b_r); also re-zeros acc for next layer.
__global__ void k_dst(const float* __restrict__ relb, int layer) {
  __shared__ float sb[NR * HD];
  for (int i = threadIdx.x; i < NR * HD; i += blockDim.x) sb[i] = relb[i];
  __syncthreads();
  float* emb = (layer == 0) ? g_emb1 : g_emb2;
  int t = blockIdx.x * 256 + threadIdx.x;
  int node = t >> 4, lane = t & 15;
  if (node >= NN) return;
  float4 a = *(float4*)(g_acc + (size_t)node * HD + lane * 4);
  #pragma unroll
  for (int r = 0; r < NR; r++) {
    float s = g_S[node * NR + r];
    float4 t4 = __ldg((const float4*)(g_T + (size_t)(5 + r) * NN * HD + (size_t)node * HD) + lane);
    float4 b4 = *(float4*)(sb + r * HD + lane * 4);
    a.x += s * (t4.x + b4.x);
    a.y += s * (t4.y + b4.y);
    a.z += s * (t4.z + b4.z);
    a.w += s * (t4.w + b4.w);
  }
  *(float4*)(emb + (size_t)node * HD + lane * 4) = a;
  *(float4*)(g_acc + (size_t)node * HD + lane * 4) = make_float4(0.f, 0.f, 0.f, 0.f);
}

// out = sum_j leaky_relu(emb_j @ outW_j + outb_j), fused over j=0..2.
__global__ void k_out(const float* __restrict__ W0, const float* __restrict__ b0,
                      const float* __restrict__ W1, const float* __restrict__ b1,
                      const float* __restrict__ W2, const float* __restrict__ b2,
                      float* __restrict__ out) {
  __shared__ __align__(16) float sA[64 * SA_STRIDE];
  __shared__ __align__(16) float sW[64 * 64];
  __shared__ float sb[64];
  int tx = threadIdx.x & 15, ty = threadIdx.x >> 4;
  int row0 = blockIdx.x * 64;
  float o[4][4] = {};
  #pragma unroll 1
  for (int j = 0; j < 3; j++) {
    const float* emb = (j == 0) ? g_emb0 : (j == 1) ? g_emb1 : g_emb2;
    const float* W = (j == 0) ? W0 : (j == 1) ? W1 : W2;
    const float* b = (j == 0) ? b0 : (j == 1) ? b1 : b2;
    __syncthreads();  // protect sb reads of previous iteration
    if (threadIdx.x < 64) sb[threadIdx.x] = b[threadIdx.x];
    float acc[4][4] = {};
    gemm_accum(emb, HD, W, row0, sA, sW, acc, tx, ty);  // internal syncs publish sb too
    #pragma unroll
    for (int i = 0; i < 4; i++)
      #pragma unroll
      for (int m = 0; m < 4; m++) {
        float z = acc[i][m] + sb[tx * 4 + m];
        o[i][m] += (z >= 0.f) ? z : NEG_SLOPE * z;
      }
  }
  #pragma unroll
  for (int i = 0; i < 4; i++) {
    int row = row0 + ty * 4 + i;
    if (row < NN)
      *(float4*)(out + (size_t)row * HD + tx * 4) =
          make_float4(o[i][0], o[i][1], o[i][2], o[i][3]);
  }
}

// ---------------------------------------------------------------------------
extern "C" void kernel_launch(void* const* d_in, const int* in_sizes, int n_in,
                              void* d_out, int out_size) {
  const float* x     = (const float*)d_in[0];
  const int*   eidx  = (const int*)d_in[1];
  const int*   etype = (const int*)d_in[2];
  const float* etime = (const float*)d_in[3];
  const float* fW    = (const float*)d_in[4];
  const float* fb    = (const float*)d_in[5];
  const float* rW1   = (const float*)d_in[6];
  const float* rb1   = (const float*)d_in[7];
  const float* rW2   = (const float*)d_in[8];
  const float* rb2   = (const float*)d_in[9];
  const float* oW0   = (const float*)d_in[10];
  const float* ob0   = (const float*)d_in[11];
  const float* oW1   = (const float*)d_in[12];
  const float* ob1   = (const float*)d_in[13];
  const float* oW2   = (const float*)d_in[14];
  const float* ob2   = (const float*)d_in[15];
  const float* lam   = (const float*)d_in[16];
  const float* beta  = (const float*)d_in[17];
  float* out = (float*)d_out;

  const int GB = (NN + 63) / 64;  // 782 row tiles
  dim3 gt(GB, 10);

  k_init<<<1024, 256>>>();
  k_wS<<<(NE + 255) / 256, 256>>>(etime, eidx, etype, lam, beta);
  k_emb0<<<GB, 256>>>(x, fW, fb);

  // layer 1
  k_trans<<<gt, 256>>>(rW1, 0);
  k_edge<<<NE * 16 / 256, 256>>>(eidx, etype);
  k_dst<<<(NN * 16 + 255) / 256, 256>>>(rb1, 0);

  // layer 2
  k_trans<<<gt, 256>>>(rW2, 1);
  k_edge<<<NE * 16 / 256, 256>>>(eidx, etype);
  k_dst<<<(NN * 16 + 255) / 256, 256>>>(rb2, 1);

  k_out<<<GB, 256>>>(oW0, ob0, oW1, ob1, oW2, ob2, out);
}